// round 2
// baseline (speedup 1.0000x reference)
#include <cuda_runtime.h>

// FeatureFusion: b=16, c=512, h=w=64 (hw=4096), fp32.
//   inter = sigmoid(D @ R^T)   (per batch: 512x512 = [512x4096]·[512x4096]^T, NT)
//   out   = inter @ D + R      (per batch: 512x4096 = [512x512]·[512x4096], NN)
// d_in[0] = rgb_feat (R), d_in[1] = depth_feat (D), per setup_inputs order.

#define BATCH 16
#define CDIM  512
#define HW    4096

#define BM 128
#define BN 128
#define BK 16
#define TM 8
#define TN 8
#define NTHREADS 256   // (BM/TM)*(BN/TN)

// Scratch for sigmoid(interaction): 16 MB static device array (no allocation).
__device__ float g_inter[(size_t)BATCH * CDIM * CDIM];

__device__ __forceinline__ float fast_sigmoid(float x) {
    // __expf saturates cleanly: exp(+inf)->inf => 0, exp(-big)->0 => 1
    return 1.0f / (1.0f + __expf(-x));
}

// ---------------------------------------------------------------------------
// GEMM1 (NT): C[i,j] = sum_s D[i,s] * R[j,s], then sigmoid, store to g_inter.
// Both operands are row-major [rows, K] with K contiguous.
// ---------------------------------------------------------------------------
__global__ __launch_bounds__(NTHREADS, 2)
void gemm1_nt_sigmoid(const float* __restrict__ depth,
                      const float* __restrict__ rgb)
{
    __shared__ float As[BK][BM + 4];
    __shared__ float Bs[BK][BN + 4];

    const int b = blockIdx.z;
    const float* A  = depth + (size_t)b * CDIM * HW;  // M x K, ld = HW
    const float* Bm = rgb   + (size_t)b * CDIM * HW;  // N x K, ld = HW
    float* C = g_inter + (size_t)b * CDIM * CDIM;

    const int tid  = threadIdx.x;
    const int row0 = blockIdx.y * BM;
    const int col0 = blockIdx.x * BN;

    // tile loader: 128 rows x 16 cols, one float4 per thread per pass (2 passes)
    const int ldRow = tid >> 2;          // 0..63
    const int ldCol = (tid & 3) << 2;    // 0,4,8,12

    const int ty = tid / (BN / TN);      // 0..15
    const int tx = tid % (BN / TN);      // 0..15

    float acc[TM][TN];
#pragma unroll
    for (int m = 0; m < TM; m++)
#pragma unroll
        for (int n = 0; n < TN; n++) acc[m][n] = 0.0f;

    for (int k0 = 0; k0 < HW; k0 += BK) {
#pragma unroll
        for (int i = 0; i < 2; i++) {
            const int r = ldRow + i * 64;
            float4 va = *(const float4*)(A  + (size_t)(row0 + r) * HW + k0 + ldCol);
            As[ldCol + 0][r] = va.x;
            As[ldCol + 1][r] = va.y;
            As[ldCol + 2][r] = va.z;
            As[ldCol + 3][r] = va.w;
            float4 vb = *(const float4*)(Bm + (size_t)(col0 + r) * HW + k0 + ldCol);
            Bs[ldCol + 0][r] = vb.x;
            Bs[ldCol + 1][r] = vb.y;
            Bs[ldCol + 2][r] = vb.z;
            Bs[ldCol + 3][r] = vb.w;
        }
        __syncthreads();

#pragma unroll
        for (int k = 0; k < BK; k++) {
            float a[TM], bb[TN];
#pragma unroll
            for (int m = 0; m < TM; m++) a[m]  = As[k][ty * TM + m];
#pragma unroll
            for (int n = 0; n < TN; n++) bb[n] = Bs[k][tx * TN + n];
#pragma unroll
            for (int m = 0; m < TM; m++)
#pragma unroll
                for (int n = 0; n < TN; n++)
                    acc[m][n] = fmaf(a[m], bb[n], acc[m][n]);
        }
        __syncthreads();
    }

#pragma unroll
    for (int m = 0; m < TM; m++) {
        const int r = row0 + ty * TM + m;
#pragma unroll
        for (int n = 0; n < TN; n += 4) {
            float4 v;
            v.x = fast_sigmoid(acc[m][n + 0]);
            v.y = fast_sigmoid(acc[m][n + 1]);
            v.z = fast_sigmoid(acc[m][n + 2]);
            v.w = fast_sigmoid(acc[m][n + 3]);
            *(float4*)(C + (size_t)r * CDIM + col0 + tx * TN + n) = v;
        }
    }
}

// ---------------------------------------------------------------------------
// GEMM2 (NN): out[i,s] = sum_d inter[i,d] * D[d,s] + R[i,s].
// A = inter (M=512, K=512, K contiguous); B = D (K=512, N=4096, N contiguous).
// ---------------------------------------------------------------------------
__global__ __launch_bounds__(NTHREADS, 2)
void gemm2_nn_add(const float* __restrict__ depth,
                  const float* __restrict__ rgb,
                  float* __restrict__ out)
{
    __shared__ float As[BK][BM + 4];
    __shared__ float Bs[BK][BN];

    const int b = blockIdx.z;
    const float* A    = g_inter + (size_t)b * CDIM * CDIM;  // M x K, ld = CDIM
    const float* Bmat = depth   + (size_t)b * CDIM * HW;    // K x N, ld = HW
    const float* Rg   = rgb     + (size_t)b * CDIM * HW;
    float* O = out + (size_t)b * CDIM * HW;

    const int tid  = threadIdx.x;
    const int row0 = blockIdx.y * BM;
    const int col0 = blockIdx.x * BN;

    // A tile loader: 128x16, transpose into SMEM
    const int aRow = tid >> 2;           // 0..63
    const int aCol = (tid & 3) << 2;     // 0,4,8,12
    // B tile loader: 16x128, direct (N contiguous)
    const int bRow = tid >> 5;           // 0..7
    const int bCol = (tid & 31) << 2;    // 0..124

    const int ty = tid / (BN / TN);
    const int tx = tid % (BN / TN);

    float acc[TM][TN];
#pragma unroll
    for (int m = 0; m < TM; m++)
#pragma unroll
        for (int n = 0; n < TN; n++) acc[m][n] = 0.0f;

    for (int k0 = 0; k0 < CDIM; k0 += BK) {
#pragma unroll
        for (int i = 0; i < 2; i++) {
            const int r = aRow + i * 64;
            float4 va = *(const float4*)(A + (size_t)(row0 + r) * CDIM + k0 + aCol);
            As[aCol + 0][r] = va.x;
            As[aCol + 1][r] = va.y;
            As[aCol + 2][r] = va.z;
            As[aCol + 3][r] = va.w;
        }
#pragma unroll
        for (int i = 0; i < 2; i++) {
            const int r = bRow + i * 8;
            float4 vb = *(const float4*)(Bmat + (size_t)(k0 + r) * HW + col0 + bCol);
            *(float4*)&Bs[r][bCol] = vb;
        }
        __syncthreads();

#pragma unroll
        for (int k = 0; k < BK; k++) {
            float a[TM], bb[TN];
#pragma unroll
            for (int m = 0; m < TM; m++) a[m]  = As[k][ty * TM + m];
#pragma unroll
            for (int n = 0; n < TN; n++) bb[n] = Bs[k][tx * TN + n];
#pragma unroll
            for (int m = 0; m < TM; m++)
#pragma unroll
                for (int n = 0; n < TN; n++)
                    acc[m][n] = fmaf(a[m], bb[n], acc[m][n]);
        }
        __syncthreads();
    }

#pragma unroll
    for (int m = 0; m < TM; m++) {
        const int r = row0 + ty * TM + m;
        const size_t rowOff = (size_t)r * HW + col0 + tx * TN;
#pragma unroll
        for (int n = 0; n < TN; n += 4) {
            float4 rv = *(const float4*)(Rg + rowOff + n);
            float4 v;
            v.x = acc[m][n + 0] + rv.x;
            v.y = acc[m][n + 1] + rv.y;
            v.z = acc[m][n + 2] + rv.z;
            v.w = acc[m][n + 3] + rv.w;
            *(float4*)(O + rowOff + n) = v;
        }
    }
}

extern "C" void kernel_launch(void* const* d_in, const int* in_sizes, int n_in,
                              void* d_out, int out_size)
{
    const float* rgb   = (const float*)d_in[0];
    const float* depth = (const float*)d_in[1];
    float* out = (float*)d_out;

    dim3 block(NTHREADS);
    dim3 g1(CDIM / BN, CDIM / BM, BATCH);   // 4 x 4 x 16
    gemm1_nt_sigmoid<<<g1, block>>>(depth, rgb);

    dim3 g2(HW / BN, CDIM / BM, BATCH);     // 32 x 4 x 16
    gemm2_nn_add<<<g2, block>>>(depth, rgb, out);
}

// round 3
// speedup vs baseline: 2.7718x; 2.7718x over previous
#include <cuda_runtime.h>
#include <cstdint>

// FeatureFusion: b=16, c=512, hw=4096, fp32.
//   inter = sigmoid(D @ R^T)  (NT, per batch 512x512, K=4096)
//   out   = inter @ D + R     (NN, per batch 512x4096, K=512)
// tf32 tensor-core implementation (mma.sync.m16n8k8) with cp.async pipeline.

#define BATCH 16
#define CDIM  512
#define HW    4096

#define BM 128
#define BN 128
#define BK 16          // 16 floats = 64B per SMEM row
#define NTH 256        // 8 warps: 2 (m) x 4 (n), warp tile 64x32

__device__ float g_inter[(size_t)BATCH * CDIM * CDIM];

// ---------------------------------------------------------------- helpers
__device__ __forceinline__ uint32_t cvta_s(const void* p) {
    return (uint32_t)__cvta_generic_to_shared(p);
}
__device__ __forceinline__ void cpa16(uint32_t s, const float* g) {
    asm volatile("cp.async.cg.shared.global [%0], [%1], 16;" :: "r"(s), "l"(g));
}
__device__ __forceinline__ void cpcommit() { asm volatile("cp.async.commit_group;"); }
template<int N> __device__ __forceinline__ void cpwait() {
    asm volatile("cp.async.wait_group %0;" :: "n"(N));
}
__device__ __forceinline__ void ldm4(uint32_t* r, uint32_t a) {
    asm volatile("ldmatrix.sync.aligned.m8n8.x4.shared.b16 {%0,%1,%2,%3}, [%4];"
        : "=r"(r[0]), "=r"(r[1]), "=r"(r[2]), "=r"(r[3]) : "r"(a));
}
__device__ __forceinline__ uint32_t f2tf_u(uint32_t u) {
    float f = __uint_as_float(u);
    uint32_t o; asm("cvt.rna.tf32.f32 %0, %1;" : "=r"(o) : "f"(f)); return o;
}
__device__ __forceinline__ uint32_t f2tf(float f) {
    uint32_t o; asm("cvt.rna.tf32.f32 %0, %1;" : "=r"(o) : "f"(f)); return o;
}
__device__ __forceinline__ void mma8(float* c, const uint32_t* a, const uint32_t* b) {
    asm volatile("mma.sync.aligned.m16n8k8.row.col.f32.tf32.tf32.f32 "
        "{%0,%1,%2,%3},{%4,%5,%6,%7},{%8,%9},{%0,%1,%2,%3};"
        : "+f"(c[0]), "+f"(c[1]), "+f"(c[2]), "+f"(c[3])
        : "r"(a[0]), "r"(a[1]), "r"(a[2]), "r"(a[3]), "r"(b[0]), "r"(b[1]));
}
__device__ __forceinline__ float fast_sigmoid(float x) {
    return 1.0f / (1.0f + __expf(-x));
}

// SW64-style swizzle on 64B rows: chunk(16B) c at row r -> c ^ ((r>>1)&3).
// ldmatrix reading 8 consecutive rows of one chunk column is conflict-free
// (rows alternate bank halves via the 64B stride; chunk XOR separates pairs).

// =======================================================================
// GEMM1 (NT): C = sigmoid(D @ R^T) -> g_inter.  Both operands k-contiguous.
// =======================================================================
#define S1 3
#define STG1_FLOATS ((BM + BN) * BK)   // 4096 floats (16 KB) per stage
#define STG1_BYTES  (STG1_FLOATS * 4)

__global__ __launch_bounds__(NTH, 1)
void gemm1_tc(const float* __restrict__ depth, const float* __restrict__ rgb)
{
    __shared__ __align__(128) float sm[S1 * STG1_FLOATS];   // 48 KB

    const int b = blockIdx.z;
    const float* Ag = depth + (size_t)b * CDIM * HW + (size_t)(blockIdx.y * BM) * HW;
    const float* Bg = rgb   + (size_t)b * CDIM * HW + (size_t)(blockIdx.x * BN) * HW;
    float* Cg = g_inter + (size_t)b * CDIM * CDIM;

    const int tid = threadIdx.x, lane = tid & 31, wid = tid >> 5;
    const int wm = wid >> 2, wn = wid & 3;

    // ---- loader mapping: 512 chunks (16B) per operand per stage, 2/thread
    const int ldRow = tid >> 2;                 // 0..63 (and +64)
    const int ldCh  = tid & 3;
    const int ldChS = ldCh ^ ((ldRow >> 1) & 3);
    const uint32_t smBase = cvta_s(sm);
    const uint32_t sO0 = (uint32_t)(ldRow * 64 + ldChS * 16);   // same swizzle at row+64
    const int gO0 = ldRow * HW + ldCh * 4;      // float offset
    // ---- fragment address precompute
    const int rlA = lane & 15, hiA = lane >> 4;
    const int swA = (rlA >> 1) & 3;
    const int cA0 = hiA ^ swA, cA1 = (2 + hiA) ^ swA;
    const uint32_t aOff = (uint32_t)((wm * 64 + rlA) * 64);
    const int rlB = (lane & 7) | ((lane & 16) >> 1);
    const int hiB = (lane >> 3) & 1;
    const int swB = (rlB >> 1) & 3;
    const int cB0 = hiB ^ swB, cB1 = (2 + hiB) ^ swB;
    const uint32_t bOff = (uint32_t)((wn * 32 + rlB) * 64);

    float acc[4][4][4];
#pragma unroll
    for (int i = 0; i < 4; i++)
#pragma unroll
        for (int j = 0; j < 4; j++)
#pragma unroll
            for (int k = 0; k < 4; k++) acc[i][j][k] = 0.0f;

    const int T = HW / BK;   // 256

    // prologue: stages 0..S1-2
#pragma unroll
    for (int p = 0; p < S1 - 1; p++) {
        uint32_t aSm = smBase + p * STG1_BYTES;
        uint32_t bSm = aSm + BM * BK * 4;
        int kc = p * BK;
        cpa16(aSm + sO0,            Ag + gO0 + kc);
        cpa16(aSm + sO0 + 64 * 64,  Ag + gO0 + 64 * HW + kc);
        cpa16(bSm + sO0,            Bg + gO0 + kc);
        cpa16(bSm + sO0 + 64 * 64,  Bg + gO0 + 64 * HW + kc);
        cpcommit();
    }

    int stage = 0;
    for (int t = 0; t < T; t++) {
        cpwait<S1 - 2>();
        __syncthreads();

        int nt = t + S1 - 1;
        if (nt < T) {
            int ns = nt % S1;
            uint32_t aSm = smBase + ns * STG1_BYTES;
            uint32_t bSm = aSm + BM * BK * 4;
            int kc = nt * BK;
            cpa16(aSm + sO0,            Ag + gO0 + kc);
            cpa16(aSm + sO0 + 64 * 64,  Ag + gO0 + 64 * HW + kc);
            cpa16(bSm + sO0,            Bg + gO0 + kc);
            cpa16(bSm + sO0 + 64 * 64,  Bg + gO0 + 64 * HW + kc);
        }
        cpcommit();

        uint32_t aS = smBase + stage * STG1_BYTES;
        uint32_t bS = aS + BM * BK * 4;
#pragma unroll
        for (int ks = 0; ks < 2; ks++) {
            const int cA = ks ? cA1 : cA0;
            const int cB = ks ? cB1 : cB0;
            uint32_t aF[4][4];
#pragma unroll
            for (int fm = 0; fm < 4; fm++) {
                ldm4(aF[fm], aS + aOff + fm * 1024 + cA * 16);
#pragma unroll
                for (int i = 0; i < 4; i++) aF[fm][i] = f2tf_u(aF[fm][i]);
            }
            uint32_t bF[4][2];
#pragma unroll
            for (int pr = 0; pr < 2; pr++) {
                uint32_t r[4];
                ldm4(r, bS + bOff + pr * 1024 + cB * 16);
                bF[pr * 2][0]     = f2tf_u(r[0]);
                bF[pr * 2][1]     = f2tf_u(r[1]);
                bF[pr * 2 + 1][0] = f2tf_u(r[2]);
                bF[pr * 2 + 1][1] = f2tf_u(r[3]);
            }
#pragma unroll
            for (int fm = 0; fm < 4; fm++)
#pragma unroll
                for (int fn = 0; fn < 4; fn++)
                    mma8(acc[fm][fn], aF[fm], bF[fn]);
        }
        stage = (stage + 1 == S1) ? 0 : stage + 1;
    }

    // epilogue: sigmoid + store
    const int gRow = blockIdx.y * BM + wm * 64 + (lane >> 2);
    const int gCol = blockIdx.x * BN + wn * 32 + (lane & 3) * 2;
#pragma unroll
    for (int fm = 0; fm < 4; fm++) {
        int r = gRow + fm * 16;
#pragma unroll
        for (int fn = 0; fn < 4; fn++) {
            int c = gCol + fn * 8;
            float2 v0 = { fast_sigmoid(acc[fm][fn][0]), fast_sigmoid(acc[fm][fn][1]) };
            float2 v1 = { fast_sigmoid(acc[fm][fn][2]), fast_sigmoid(acc[fm][fn][3]) };
            *(float2*)(Cg + (size_t)r * CDIM + c)       = v0;
            *(float2*)(Cg + (size_t)(r + 8) * CDIM + c) = v1;
        }
    }
}

// =======================================================================
// GEMM2 (NN): out = inter @ D + R.  A k-contiguous; B n-contiguous.
// B tile in SMEM: [BK][136] float (stride 136 -> 8-bank skew, conflict-free
// direct-LDS fragment reads).
// =======================================================================
#define S2 2
#define BSTR 136
#define STG2_FLOATS (BM * BK + BK * BSTR)   // 2048 + 2176 = 4224
#define STG2_BYTES  (STG2_FLOATS * 4)

__global__ __launch_bounds__(NTH, 1)
void gemm2_tc(const float* __restrict__ depth, const float* __restrict__ rgb,
              float* __restrict__ out)
{
    __shared__ __align__(128) float sm[S2 * STG2_FLOATS];   // 33 KB

    const int b = blockIdx.z;
    const float* Ag = g_inter + (size_t)b * CDIM * CDIM + (size_t)(blockIdx.y * BM) * CDIM;
    const float* Bg = depth + (size_t)b * CDIM * HW + blockIdx.x * BN;
    const float* Rg = rgb + (size_t)b * CDIM * HW;
    float* Og = out + (size_t)b * CDIM * HW;

    const int tid = threadIdx.x, lane = tid & 31, wid = tid >> 5;
    const int wm = wid >> 2, wn = wid & 3;

    // A loader (swizzled 64B rows)
    const int aRow = tid >> 2, aCh = tid & 3;
    const int aChS = aCh ^ ((aRow >> 1) & 3);
    const uint32_t smBase = cvta_s(sm);
    const uint32_t aSO = (uint32_t)(aRow * 64 + aChS * 16);
    const int aGO = aRow * CDIM + aCh * 4;
    // B loader: 512 chunks, [k][n] rows of 512B stored at stride 544B
    const int bRow = tid >> 5;             // 0..7 (and +8)
    const int bChk = tid & 31;
    const uint32_t bSO = (uint32_t)(bRow * (BSTR * 4) + bChk * 16);
    const int bGO = bRow * HW + bChk * 4;
    // A frag addressing
    const int rlA = lane & 15, hiA = lane >> 4;
    const int swA = (rlA >> 1) & 3;
    const int cA0 = hiA ^ swA, cA1 = (2 + hiA) ^ swA;
    const uint32_t aOff = (uint32_t)((wm * 64 + rlA) * 64);
    // B frag LDS indices
    const int bK = lane & 3;
    const int bN = wn * 32 + (lane >> 2);

    float acc[4][4][4];
#pragma unroll
    for (int i = 0; i < 4; i++)
#pragma unroll
        for (int j = 0; j < 4; j++)
#pragma unroll
            for (int k = 0; k < 4; k++) acc[i][j][k] = 0.0f;

    const int T = CDIM / BK;   // 32

    // prologue
    {
        uint32_t aSm = smBase;
        uint32_t bSm = aSm + BM * BK * 4;
        cpa16(aSm + aSO,           Ag + aGO);
        cpa16(aSm + aSO + 64 * 64, Ag + aGO + 64 * CDIM);
        cpa16(bSm + bSO,                  Bg + bGO);
        cpa16(bSm + bSO + 8 * BSTR * 4,   Bg + bGO + 8 * HW);
        cpcommit();
    }

    int stage = 0;
    for (int t = 0; t < T; t++) {
        cpwait<S2 - 2>();
        __syncthreads();

        int nt = t + S2 - 1;
        if (nt < T) {
            int ns = nt % S2;
            uint32_t aSm = smBase + ns * STG2_BYTES;
            uint32_t bSm = aSm + BM * BK * 4;
            int kc = nt * BK;
            cpa16(aSm + aSO,           Ag + aGO + kc);
            cpa16(aSm + aSO + 64 * 64, Ag + aGO + 64 * CDIM + kc);
            cpa16(bSm + bSO,                Bg + bGO + (size_t)kc * HW);
            cpa16(bSm + bSO + 8 * BSTR * 4, Bg + bGO + (size_t)(kc + 8) * HW);
        }
        cpcommit();

        uint32_t aS = smBase + stage * STG2_BYTES;
        const float* bSf = sm + stage * STG2_FLOATS + BM * BK;
#pragma unroll
        for (int ks = 0; ks < 2; ks++) {
            const int cA = ks ? cA1 : cA0;
            uint32_t aF[4][4];
#pragma unroll
            for (int fm = 0; fm < 4; fm++) {
                ldm4(aF[fm], aS + aOff + fm * 1024 + cA * 16);
#pragma unroll
                for (int i = 0; i < 4; i++) aF[fm][i] = f2tf_u(aF[fm][i]);
            }
            uint32_t bF[4][2];
#pragma unroll
            for (int fn = 0; fn < 4; fn++) {
                bF[fn][0] = f2tf(bSf[(8 * ks + bK) * BSTR     + bN + fn * 8]);
                bF[fn][1] = f2tf(bSf[(8 * ks + 4 + bK) * BSTR + bN + fn * 8]);
            }
#pragma unroll
            for (int fm = 0; fm < 4; fm++)
#pragma unroll
                for (int fn = 0; fn < 4; fn++)
                    mma8(acc[fm][fn], aF[fm], bF[fn]);
        }
        stage ^= 1;
    }

    // epilogue: + R, store
    const int gRow = blockIdx.y * BM + wm * 64 + (lane >> 2);
    const int gCol = blockIdx.x * BN + wn * 32 + (lane & 3) * 2;
#pragma unroll
    for (int fm = 0; fm < 4; fm++) {
        int r = gRow + fm * 16;
#pragma unroll
        for (int fn = 0; fn < 4; fn++) {
            int c = gCol + fn * 8;
            size_t o0 = (size_t)r * HW + c;
            size_t o1 = (size_t)(r + 8) * HW + c;
            float2 rv0 = *(const float2*)(Rg + o0);
            float2 rv1 = *(const float2*)(Rg + o1);
            float2 v0 = { acc[fm][fn][0] + rv0.x, acc[fm][fn][1] + rv0.y };
            float2 v1 = { acc[fm][fn][2] + rv1.x, acc[fm][fn][3] + rv1.y };
            *(float2*)(Og + o0) = v0;
            *(float2*)(Og + o1) = v1;
        }
    }
}

extern "C" void kernel_launch(void* const* d_in, const int* in_sizes, int n_in,
                              void* d_out, int out_size)
{
    const float* rgb   = (const float*)d_in[0];
    const float* depth = (const float*)d_in[1];
    float* out = (float*)d_out;

    dim3 block(NTH);
    dim3 g1(CDIM / BN, CDIM / BM, BATCH);   // 4 x 4 x 16
    gemm1_tc<<<g1, block>>>(depth, rgb);

    dim3 g2(HW / BN, CDIM / BM, BATCH);     // 32 x 4 x 16
    gemm2_tc<<<g2, block>>>(depth, rgb, out);
}

// round 12
// speedup vs baseline: 3.4230x; 1.2349x over previous
#include <cuda_runtime.h>
#include <cstdint>

// FeatureFusion: b=16, c=512, hw=4096, fp32.
//   inter = sigmoid(D @ R^T)  (NT, per batch 512x512, K=4096)
//   out   = inter @ D + R     (NN, per batch 512x4096, K=512)
// tf32 mma.sync.m16n8k8 + cp.async pipeline.
// R6: 2 CTAs/SM (128-reg cap), g_inter pre-rounded tf32 (GEMM2 A-path cvt-free),
//     GEMM2 pipeline deepened to 3 stages.

#define BATCH 16
#define CDIM  512
#define HW    4096

#define BM 128
#define BN 128
#define BK 16          // 16 floats = 64B per SMEM row
#define NTH 256        // 8 warps: 2 (m) x 4 (n), warp tile 64x32

__device__ float g_inter[(size_t)BATCH * CDIM * CDIM];

// ---------------------------------------------------------------- helpers
__device__ __forceinline__ uint32_t cvta_s(const void* p) {
    return (uint32_t)__cvta_generic_to_shared(p);
}
__device__ __forceinline__ void cpa16(uint32_t s, const float* g) {
    asm volatile("cp.async.cg.shared.global [%0], [%1], 16;" :: "r"(s), "l"(g));
}
__device__ __forceinline__ void cpcommit() { asm volatile("cp.async.commit_group;"); }
template<int N> __device__ __forceinline__ void cpwait() {
    asm volatile("cp.async.wait_group %0;" :: "n"(N));
}
__device__ __forceinline__ void ldm4(uint32_t* r, uint32_t a) {
    asm volatile("ldmatrix.sync.aligned.m8n8.x4.shared.b16 {%0,%1,%2,%3}, [%4];"
        : "=r"(r[0]), "=r"(r[1]), "=r"(r[2]), "=r"(r[3]) : "r"(a));
}
__device__ __forceinline__ uint32_t f2tf_u(uint32_t u) {
    float f = __uint_as_float(u);
    uint32_t o; asm("cvt.rna.tf32.f32 %0, %1;" : "=r"(o) : "f"(f)); return o;
}
__device__ __forceinline__ uint32_t f2tf(float f) {
    uint32_t o; asm("cvt.rna.tf32.f32 %0, %1;" : "=r"(o) : "f"(f)); return o;
}
__device__ __forceinline__ void mma8(float* c, const uint32_t* a, const uint32_t* b) {
    asm volatile("mma.sync.aligned.m16n8k8.row.col.f32.tf32.tf32.f32 "
        "{%0,%1,%2,%3},{%4,%5,%6,%7},{%8,%9},{%0,%1,%2,%3};"
        : "+f"(c[0]), "+f"(c[1]), "+f"(c[2]), "+f"(c[3])
        : "r"(a[0]), "r"(a[1]), "r"(a[2]), "r"(a[3]), "r"(b[0]), "r"(b[1]));
}
__device__ __forceinline__ float fast_sigmoid(float x) {
    return 1.0f / (1.0f + __expf(-x));
}

// SW64-style swizzle on 64B rows: chunk(16B) c at row r -> c ^ ((r>>1)&3).

// =======================================================================
// GEMM1 (NT): C = tf32_round(sigmoid(D @ R^T)) -> g_inter.
// =======================================================================
#define S1 3
#define STG1_FLOATS ((BM + BN) * BK)   // 4096 floats (16 KB) per stage
#define STG1_BYTES  (STG1_FLOATS * 4)

__global__ __launch_bounds__(NTH, 2)
void gemm1_tc(const float* __restrict__ depth, const float* __restrict__ rgb)
{
    __shared__ __align__(128) float sm[S1 * STG1_FLOATS];   // 48 KB

    const int b = blockIdx.z;
    const float* Ag = depth + (size_t)b * CDIM * HW + (size_t)(blockIdx.y * BM) * HW;
    const float* Bg = rgb   + (size_t)b * CDIM * HW + (size_t)(blockIdx.x * BN) * HW;
    float* Cg = g_inter + (size_t)b * CDIM * CDIM;

    const int tid = threadIdx.x, lane = tid & 31, wid = tid >> 5;
    const int wm = wid >> 2, wn = wid & 3;

    // loader mapping: 512 chunks (16B) per operand per stage, 2/thread
    const int ldRow = tid >> 2;                 // 0..63 (and +64)
    const int ldCh  = tid & 3;
    const int ldChS = ldCh ^ ((ldRow >> 1) & 3);
    const uint32_t smBase = cvta_s(sm);
    const uint32_t sO0 = (uint32_t)(ldRow * 64 + ldChS * 16);
    const int gO0 = ldRow * HW + ldCh * 4;
    // fragment address precompute
    const int rlA = lane & 15, hiA = lane >> 4;
    const int swA = (rlA >> 1) & 3;
    const int cA0 = hiA ^ swA, cA1 = (2 + hiA) ^ swA;
    const uint32_t aOff = (uint32_t)((wm * 64 + rlA) * 64);
    const int rlB = (lane & 7) | ((lane & 16) >> 1);
    const int hiB = (lane >> 3) & 1;
    const int swB = (rlB >> 1) & 3;
    const int cB0 = hiB ^ swB, cB1 = (2 + hiB) ^ swB;
    const uint32_t bOff = (uint32_t)((wn * 32 + rlB) * 64);

    float acc[4][4][4];
#pragma unroll
    for (int i = 0; i < 4; i++)
#pragma unroll
        for (int j = 0; j < 4; j++)
#pragma unroll
            for (int k = 0; k < 4; k++) acc[i][j][k] = 0.0f;

    const int T = HW / BK;   // 256

#pragma unroll
    for (int p = 0; p < S1 - 1; p++) {
        uint32_t aSm = smBase + p * STG1_BYTES;
        uint32_t bSm = aSm + BM * BK * 4;
        int kc = p * BK;
        cpa16(aSm + sO0,            Ag + gO0 + kc);
        cpa16(aSm + sO0 + 64 * 64,  Ag + gO0 + 64 * HW + kc);
        cpa16(bSm + sO0,            Bg + gO0 + kc);
        cpa16(bSm + sO0 + 64 * 64,  Bg + gO0 + 64 * HW + kc);
        cpcommit();
    }

    int stage = 0;
    for (int t = 0; t < T; t++) {
        cpwait<S1 - 2>();
        __syncthreads();

        int nt = t + S1 - 1;
        if (nt < T) {
            int ns = nt % S1;
            uint32_t aSm = smBase + ns * STG1_BYTES;
            uint32_t bSm = aSm + BM * BK * 4;
            int kc = nt * BK;
            cpa16(aSm + sO0,            Ag + gO0 + kc);
            cpa16(aSm + sO0 + 64 * 64,  Ag + gO0 + 64 * HW + kc);
            cpa16(bSm + sO0,            Bg + gO0 + kc);
            cpa16(bSm + sO0 + 64 * 64,  Bg + gO0 + 64 * HW + kc);
        }
        cpcommit();

        uint32_t aS = smBase + stage * STG1_BYTES;
        uint32_t bS = aS + BM * BK * 4;
#pragma unroll
        for (int ks = 0; ks < 2; ks++) {
            const int cA = ks ? cA1 : cA0;
            const int cB = ks ? cB1 : cB0;
            uint32_t aF[4][4];
#pragma unroll
            for (int fm = 0; fm < 4; fm++) {
                ldm4(aF[fm], aS + aOff + fm * 1024 + cA * 16);
#pragma unroll
                for (int i = 0; i < 4; i++) aF[fm][i] = f2tf_u(aF[fm][i]);
            }
            uint32_t bF[4][2];
#pragma unroll
            for (int pr = 0; pr < 2; pr++) {
                uint32_t r[4];
                ldm4(r, bS + bOff + pr * 1024 + cB * 16);
                bF[pr * 2][0]     = f2tf_u(r[0]);
                bF[pr * 2][1]     = f2tf_u(r[1]);
                bF[pr * 2 + 1][0] = f2tf_u(r[2]);
                bF[pr * 2 + 1][1] = f2tf_u(r[3]);
            }
#pragma unroll
            for (int fm = 0; fm < 4; fm++)
#pragma unroll
                for (int fn = 0; fn < 4; fn++)
                    mma8(acc[fm][fn], aF[fm], bF[fn]);
        }
        stage = (stage + 1 == S1) ? 0 : stage + 1;
    }

    // epilogue: sigmoid, round to tf32 (so GEMM2 can skip A-cvt), store
    const int gRow = blockIdx.y * BM + wm * 64 + (lane >> 2);
    const int gCol = blockIdx.x * BN + wn * 32 + (lane & 3) * 2;
#pragma unroll
    for (int fm = 0; fm < 4; fm++) {
        int r = gRow + fm * 16;
#pragma unroll
        for (int fn = 0; fn < 4; fn++) {
            int c = gCol + fn * 8;
            float2 v0, v1;
            v0.x = __uint_as_float(f2tf(fast_sigmoid(acc[fm][fn][0])));
            v0.y = __uint_as_float(f2tf(fast_sigmoid(acc[fm][fn][1])));
            v1.x = __uint_as_float(f2tf(fast_sigmoid(acc[fm][fn][2])));
            v1.y = __uint_as_float(f2tf(fast_sigmoid(acc[fm][fn][3])));
            *(float2*)(Cg + (size_t)r * CDIM + c)       = v0;
            *(float2*)(Cg + (size_t)(r + 8) * CDIM + c) = v1;
        }
    }
}

// =======================================================================
// GEMM2 (NN): out = inter @ D + R. A (inter) already tf32-rounded -> no cvt.
// 3-stage pipeline (49.5 KB SMEM, fits 2 CTAs/SM).
// =======================================================================
#define S2 3
#define BSTR 136
#define STG2_FLOATS (BM * BK + BK * BSTR)   // 4224
#define STG2_BYTES  (STG2_FLOATS * 4)

__global__ __launch_bounds__(NTH, 2)
void gemm2_tc(const float* __restrict__ depth, const float* __restrict__ rgb,
              float* __restrict__ out)
{
    __shared__ __align__(128) float sm[S2 * STG2_FLOATS];   // 49.5 KB

    const int b = blockIdx.z;
    const float* Ag = g_inter + (size_t)b * CDIM * CDIM + (size_t)(blockIdx.y * BM) * CDIM;
    const float* Bg = depth + (size_t)b * CDIM * HW + blockIdx.x * BN;
    const float* Rg = rgb + (size_t)b * CDIM * HW;
    float* Og = out + (size_t)b * CDIM * HW;

    const int tid = threadIdx.x, lane = tid & 31, wid = tid >> 5;
    const int wm = wid >> 2, wn = wid & 3;

    const int aRow = tid >> 2, aCh = tid & 3;
    const int aChS = aCh ^ ((aRow >> 1) & 3);
    const uint32_t smBase = cvta_s(sm);
    const uint32_t aSO = (uint32_t)(aRow * 64 + aChS * 16);
    const int aGO = aRow * CDIM + aCh * 4;
    const int bRow = tid >> 5;
    const int bChk = tid & 31;
    const uint32_t bSO = (uint32_t)(bRow * (BSTR * 4) + bChk * 16);
    const int bGO = bRow * HW + bChk * 4;
    const int rlA = lane & 15, hiA = lane >> 4;
    const int swA = (rlA >> 1) & 3;
    const int cA0 = hiA ^ swA, cA1 = (2 + hiA) ^ swA;
    const uint32_t aOff = (uint32_t)((wm * 64 + rlA) * 64);
    const int bK = lane & 3;
    const int bN = wn * 32 + (lane >> 2);

    float acc[4][4][4];
#pragma unroll
    for (int i = 0; i < 4; i++)
#pragma unroll
        for (int j = 0; j < 4; j++)
#pragma unroll
            for (int k = 0; k < 4; k++) acc[i][j][k] = 0.0f;

    const int T = CDIM / BK;   // 32

#pragma unroll
    for (int p = 0; p < S2 - 1; p++) {
        uint32_t aSm = smBase + p * STG2_BYTES;
        uint32_t bSm = aSm + BM * BK * 4;
        int kc = p * BK;
        cpa16(aSm + aSO,           Ag + aGO + kc);
        cpa16(aSm + aSO + 64 * 64, Ag + aGO + 64 * CDIM + kc);
        cpa16(bSm + bSO,                Bg + bGO + (size_t)kc * HW);
        cpa16(bSm + bSO + 8 * BSTR * 4, Bg + bGO + (size_t)(kc + 8) * HW);
        cpcommit();
    }

    int stage = 0;
    for (int t = 0; t < T; t++) {
        cpwait<S2 - 2>();
        __syncthreads();

        int nt = t + S2 - 1;
        if (nt < T) {
            int ns = nt % S2;
            uint32_t aSm = smBase + ns * STG2_BYTES;
            uint32_t bSm = aSm + BM * BK * 4;
            int kc = nt * BK;
            cpa16(aSm + aSO,           Ag + aGO + kc);
            cpa16(aSm + aSO + 64 * 64, Ag + aGO + 64 * CDIM + kc);
            cpa16(bSm + bSO,                Bg + bGO + (size_t)kc * HW);
            cpa16(bSm + bSO + 8 * BSTR * 4, Bg + bGO + (size_t)(kc + 8) * HW);
        }
        cpcommit();

        uint32_t aS = smBase + stage * STG2_BYTES;
        const float* bSf = sm + stage * STG2_FLOATS + BM * BK;
#pragma unroll
        for (int ks = 0; ks < 2; ks++) {
            const int cA = ks ? cA1 : cA0;
            uint32_t aF[4][4];
#pragma unroll
            for (int fm = 0; fm < 4; fm++)
                ldm4(aF[fm], aS + aOff + fm * 1024 + cA * 16);  // pre-rounded: no cvt
            uint32_t bF[4][2];
#pragma unroll
            for (int fn = 0; fn < 4; fn++) {
                bF[fn][0] = f2tf(bSf[(8 * ks + bK) * BSTR     + bN + fn * 8]);
                bF[fn][1] = f2tf(bSf[(8 * ks + 4 + bK) * BSTR + bN + fn * 8]);
            }
#pragma unroll
            for (int fm = 0; fm < 4; fm++)
#pragma unroll
                for (int fn = 0; fn < 4; fn++)
                    mma8(acc[fm][fn], aF[fm], bF[fn]);
        }
        stage = (stage + 1 == S2) ? 0 : stage + 1;
    }

    // epilogue: + R, store
    const int gRow = blockIdx.y * BM + wm * 64 + (lane >> 2);
    const int gCol = blockIdx.x * BN + wn * 32 + (lane & 3) * 2;
#pragma unroll
    for (int fm = 0; fm < 4; fm++) {
        int r = gRow + fm * 16;
#pragma unroll
        for (int fn = 0; fn < 4; fn++) {
            int c = gCol + fn * 8;
            size_t o0 = (size_t)r * HW + c;
            size_t o1 = (size_t)(r + 8) * HW + c;
            float2 rv0 = *(const float2*)(Rg + o0);
            float2 rv1 = *(const float2*)(Rg + o1);
            float2 v0 = { acc[fm][fn][0] + rv0.x, acc[fm][fn][1] + rv0.y };
            float2 v1 = { acc[fm][fn][2] + rv1.x, acc[fm][fn][3] + rv1.y };
            *(float2*)(Og + o0) = v0;
            *(float2*)(Og + o1) = v1;
        }
    }
}

extern "C" void kernel_launch(void* const* d_in, const int* in_sizes, int n_in,
                              void* d_out, int out_size)
{
    const float* rgb   = (const float*)d_in[0];
    const float* depth = (const float*)d_in[1];
    float* out = (float*)d_out;

    dim3 block(NTH);
    dim3 g1(CDIM / BN, CDIM / BM, BATCH);   // 4 x 4 x 16
    gemm1_tc<<<g1, block>>>(depth, rgb);

    dim3 g2(HW / BN, CDIM / BM, BATCH);     // 32 x 4 x 16
    gemm2_tc<<<g2, block>>>(depth, rgb, out);
}